// round 10
// baseline (speedup 1.0000x reference)
#include <cuda_runtime.h>
#include <cuda_bf16.h>
#include <cstdint>

#define BSZ 4
#define SEQ 2048
#define EMB 1024
#define HD  64
#define MTOT (BSZ * SEQ)

// bf16 split weights (x is converted in-kernel)
__device__ __nv_bfloat16 w_hi[192 * EMB];
__device__ __nv_bfloat16 w_lo[192 * EMB];
// projection outputs: Q,K transposed [dim][global row], V row-major
__device__ float g_qT[HD * MTOT];
__device__ float g_kT[HD * MTOT];
__device__ float g_vs[MTOT * HD];
// vmean
__device__ float g_vpart[BSZ * 32 * HD];
__device__ float g_vmean[BSZ * HD];
// attention split-key partials: uniform 256-key chunks -> 144 jobs/batch
#define NJOBS 576
__device__ float g_pm[NJOBS * 64];
__device__ float g_pl[NJOBS * 64];
__device__ float g_po[NJOBS * 64 * 64];

typedef unsigned long long u64;

__device__ __forceinline__ u64 splat2(float x) {
    u64 r; asm("mov.b64 %0, {%1, %1};" : "=l"(r) : "f"(x)); return r;
}
__device__ __forceinline__ u64 pack2(float lo, float hi) {
    u64 r; asm("mov.b64 %0, {%1, %2};" : "=l"(r) : "f"(lo), "f"(hi)); return r;
}
__device__ __forceinline__ void fma2(u64& d, u64 a, u64 b) {
    asm("fma.rn.f32x2 %0, %1, %2, %0;" : "+l"(d) : "l"(a), "l"(b));
}
__device__ __forceinline__ void mul2(u64& d, u64 s) {
    asm("mul.rn.f32x2 %0, %0, %1;" : "+l"(d) : "l"(s));
}
__device__ __forceinline__ void unpack2(u64 v, float& lo, float& hi) {
    asm("mov.b64 {%0, %1}, %2;" : "=f"(lo), "=f"(hi) : "l"(v));
}
__device__ __forceinline__ uint32_t smem_u32(const void* p) {
    uint32_t a;
    asm("{ .reg .u64 t; cvta.to.shared.u64 t, %1; cvt.u32.u64 %0, t; }"
        : "=r"(a) : "l"(p));
    return a;
}

// ---- portable tensor-core helpers ----------------------------------------
__device__ __forceinline__ void mma_bf16(float* d, const uint32_t* a,
                                         const uint32_t* b) {
    asm volatile(
        "mma.sync.aligned.m16n8k16.row.col.f32.bf16.bf16.f32 "
        "{%0,%1,%2,%3}, {%4,%5,%6,%7}, {%8,%9}, {%0,%1,%2,%3};"
        : "+f"(d[0]), "+f"(d[1]), "+f"(d[2]), "+f"(d[3])
        : "r"(a[0]), "r"(a[1]), "r"(a[2]), "r"(a[3]), "r"(b[0]), "r"(b[1]));
}
__device__ __forceinline__ void ldsm4(uint32_t* r, uint32_t addr) {
    asm volatile("ldmatrix.sync.aligned.m8n8.x4.shared.b16 {%0,%1,%2,%3}, [%4];"
                 : "=r"(r[0]), "=r"(r[1]), "=r"(r[2]), "=r"(r[3]) : "r"(addr));
}
__device__ __forceinline__ void cp16(uint32_t smaddr, const void* g) {
    asm volatile("cp.async.ca.shared.global [%0], [%1], 16;"
                 :: "r"(smaddr), "l"(g));
}
#define CP_COMMIT()  asm volatile("cp.async.commit_group;" ::: "memory")
#define CP_WAIT(n)   asm volatile("cp.async.wait_group %0;" :: "n"(n) : "memory")

// ---- bf16 hi/lo split of a float4 ----------------------------------------
__device__ __forceinline__ void split4(float4 v, uint2& oh, uint2& ol) {
    __nv_bfloat16 h0 = __float2bfloat16_rn(v.x);
    __nv_bfloat16 h1 = __float2bfloat16_rn(v.y);
    __nv_bfloat16 h2 = __float2bfloat16_rn(v.z);
    __nv_bfloat16 h3 = __float2bfloat16_rn(v.w);
    __nv_bfloat16 l0 = __float2bfloat16_rn(v.x - __bfloat162float(h0));
    __nv_bfloat16 l1 = __float2bfloat16_rn(v.y - __bfloat162float(h1));
    __nv_bfloat16 l2 = __float2bfloat16_rn(v.z - __bfloat162float(h2));
    __nv_bfloat16 l3 = __float2bfloat16_rn(v.w - __bfloat162float(h3));
    oh.x = ((uint32_t)__bfloat16_as_ushort(h1) << 16) | __bfloat16_as_ushort(h0);
    oh.y = ((uint32_t)__bfloat16_as_ushort(h3) << 16) | __bfloat16_as_ushort(h2);
    ol.x = ((uint32_t)__bfloat16_as_ushort(l1) << 16) | __bfloat16_as_ushort(l0);
    ol.y = ((uint32_t)__bfloat16_as_ushort(l3) << 16) | __bfloat16_as_ushort(l2);
}

// ---------------------------------------------------------------------------
// Kernel B: convert stacked W -> hi/lo bf16.
// ---------------------------------------------------------------------------
__global__ __launch_bounds__(256) void convert_w_kernel(
    const float* __restrict__ Wq, const float* __restrict__ Wk,
    const float* __restrict__ Wv)
{
    const int row = blockIdx.x;
    const float* src = (row < 64) ? (Wq + (size_t)row * EMB)
                     : (row < 128) ? (Wk + (size_t)(row - 64) * EMB)
                                   : (Wv + (size_t)(row - 128) * EMB);
    const int i = threadIdx.x;
    float4 v = reinterpret_cast<const float4*>(src)[i];
    uint2 oh, ol;
    split4(v, oh, ol);
    reinterpret_cast<uint2*>(w_hi)[(size_t)row * (EMB / 4) + i] = oh;
    reinterpret_cast<uint2*>(w_lo)[(size_t)row * (EMB / 4) + i] = ol;
}

// ---------------------------------------------------------------------------
// Kernel C: QKV GEMM via mma.sync bf16 (3-term split), x converted in-kernel.
// grid 128, 256 threads (2 M x 4 N warps). Tile M=64, N=192, K chunks 64.
// ---------------------------------------------------------------------------
#define GPITCH 144
#define OFF_AH 0
#define OFF_AL 9216
#define OFF_BH 18432
#define OFF_BL 46080
#define GBUF   73728
#define GEMM_SMEM (2 * GBUF)
#define CHUNKS 16

__device__ __forceinline__ void ldA_chunk(float4* areg, const float* __restrict__ x,
                                          int c, int row0, int tid)
{
#pragma unroll
    for (int u = 0; u < 4; u++) {
        int idx = tid + u * 256, r = idx >> 4, seg = idx & 15;
        areg[u] = *reinterpret_cast<const float4*>(
            &x[(size_t)(row0 + r) * EMB + c * 64 + seg * 4]);
    }
}

__device__ __forceinline__ void stsA_chunk(char* buf, const float4* areg, int tid)
{
#pragma unroll
    for (int u = 0; u < 4; u++) {
        int idx = tid + u * 256, r = idx >> 4, seg = idx & 15;
        uint2 oh, ol;
        split4(areg[u], oh, ol);
        *reinterpret_cast<uint2*>(buf + OFF_AH + r * GPITCH + seg * 8) = oh;
        *reinterpret_cast<uint2*>(buf + OFF_AL + r * GPITCH + seg * 8) = ol;
    }
}

__device__ __forceinline__ void stage_B(uint32_t bufb, int c, int tid)
{
#pragma unroll
    for (int u = 0; u < 6; u++) {
        int idx = tid + u * 256, r = idx >> 3, seg = idx & 7;
        uint32_t dst = r * GPITCH + seg * 16;
        cp16(bufb + OFF_BH + dst, &w_hi[(size_t)r * EMB + c * 64 + seg * 8]);
        cp16(bufb + OFF_BL + dst, &w_lo[(size_t)r * EMB + c * 64 + seg * 8]);
    }
}

__global__ __launch_bounds__(256) void qkv_gemm_kernel(const float* __restrict__ x)
{
    extern __shared__ char smg[];
    const uint32_t smb = smem_u32(smg);
    const int tid  = threadIdx.x;
    const int lane = tid & 31;
    const int w    = tid >> 5;
    const int wm   = w & 1;
    const int wn   = w >> 1;
    const int row0 = blockIdx.x * 64;

    float acc[2][6][4];
#pragma unroll
    for (int mm = 0; mm < 2; mm++)
#pragma unroll
        for (int nn = 0; nn < 6; nn++)
#pragma unroll
            for (int q = 0; q < 4; q++) acc[mm][nn][q] = 0.f;

    const int g01 = (lane >> 3) & 1;
    const int g23 = (lane >> 4);
    const int tr  = lane & 7;

    float4 areg[4];
    ldA_chunk(areg, x, 0, row0, tid);
    stsA_chunk(smg, areg, tid);
    stage_B(smb, 0, tid);
    CP_COMMIT();

    for (int c = 0; c < CHUNKS; c++) {
        const uint32_t bufb = smb + (c & 1) * GBUF;
        if (c < CHUNKS - 1) {
            ldA_chunk(areg, x, c + 1, row0, tid);
            stage_B(smb + ((c + 1) & 1) * GBUF, c + 1, tid);
            CP_COMMIT();
            CP_WAIT(1);
        } else {
            CP_WAIT(0);
        }
        __syncthreads();

#pragma unroll
        for (int pass = 0; pass < 3; pass++) {
            const uint32_t aoff = (pass == 2) ? OFF_AL : OFF_AH;
            const uint32_t boff = (pass == 1) ? OFF_BL : OFF_BH;
#pragma unroll
            for (int ks = 0; ks < 4; ks++) {
                uint32_t afr[2][4];
#pragma unroll
                for (int mm = 0; mm < 2; mm++) {
                    uint32_t addr = bufb + aoff
                        + (uint32_t)(wm * 32 + mm * 16 + g01 * 8 + tr) * GPITCH
                        + (uint32_t)(ks * 16 + g23 * 8) * 2;
                    ldsm4(afr[mm], addr);
                }
                uint32_t bfr[3][4];
#pragma unroll
                for (int ng = 0; ng < 3; ng++) {
                    uint32_t addr = bufb + boff
                        + (uint32_t)(wn * 48 + ng * 16 + g23 * 8 + tr) * GPITCH
                        + (uint32_t)(ks * 16 + g01 * 8) * 2;
                    ldsm4(bfr[ng], addr);
                }
#pragma unroll
                for (int mm = 0; mm < 2; mm++)
#pragma unroll
                    for (int nn = 0; nn < 6; nn++)
                        mma_bf16(acc[mm][nn], afr[mm], &bfr[nn >> 1][(nn & 1) * 2]);
            }
        }
        if (c < CHUNKS - 1)
            stsA_chunk(smg + ((c + 1) & 1) * GBUF, areg, tid);
        __syncthreads();
    }

    // epilogue
    const int mrow = lane >> 2;
    const int ncol = 2 * (lane & 3);
#pragma unroll
    for (int mm = 0; mm < 2; mm++) {
#pragma unroll
        for (int nn = 0; nn < 6; nn++) {
            const int n = wn * 48 + nn * 8 + ncol;
            const int m = row0 + wm * 32 + mm * 16 + mrow;
            const float* cvals = acc[mm][nn];
            if (n < 64) {
                g_qT[(size_t)n * MTOT + m]           = cvals[0];
                g_qT[(size_t)(n + 1) * MTOT + m]     = cvals[1];
                g_qT[(size_t)n * MTOT + m + 8]       = cvals[2];
                g_qT[(size_t)(n + 1) * MTOT + m + 8] = cvals[3];
            } else if (n < 128) {
                const int nk = n - 64;
                g_kT[(size_t)nk * MTOT + m]           = cvals[0];
                g_kT[(size_t)(nk + 1) * MTOT + m]     = cvals[1];
                g_kT[(size_t)nk * MTOT + m + 8]       = cvals[2];
                g_kT[(size_t)(nk + 1) * MTOT + m + 8] = cvals[3];
            } else {
                const int nv = n - 128;
                *reinterpret_cast<float2*>(&g_vs[(size_t)m * HD + nv]) =
                    make_float2(cvals[0], cvals[1]);
                *reinterpret_cast<float2*>(&g_vs[(size_t)(m + 8) * HD + nv]) =
                    make_float2(cvals[2], cvals[3]);
            }
        }
    }
}

// ---------------------------------------------------------------------------
// Kernel D: per-batch mean of V rows (parallel).
// ---------------------------------------------------------------------------
__global__ __launch_bounds__(256) void vmean1_kernel()
{
    const int b = blockIdx.x;
    const int c = blockIdx.y;                // 64-row chunk
    const int d = threadIdx.x & 63;
    const int sub = threadIdx.x >> 6;
    float s = 0.f;
    const int i0 = c * 64 + sub * 16;
#pragma unroll 4
    for (int i = i0; i < i0 + 16; i++)
        s += g_vs[((size_t)b * SEQ + i) * HD + d];
    __shared__ float red[256];
    red[threadIdx.x] = s;
    __syncthreads();
    if (sub == 0)
        g_vpart[(b * 32 + c) * HD + d] =
            red[d] + red[64 + d] + red[128 + d] + red[192 + d];
}

__global__ __launch_bounds__(256) void vmean2_kernel()
{
    const int b = blockIdx.x;
    const int d = threadIdx.x & 63;
    const int sub = threadIdx.x >> 6;
    float s = 0.f;
#pragma unroll
    for (int c = sub * 8; c < sub * 8 + 8; c++)
        s += g_vpart[(b * 32 + c) * HD + d];
    __shared__ float red[256];
    red[threadIdx.x] = s;
    __syncthreads();
    if (sub == 0)
        g_vmean[b * HD + d] =
            (red[d] + red[64 + d] + red[128 + d] + red[192 + d]) * (1.0f / SEQ);
}

// ---------------------------------------------------------------------------
// Kernel E: attention partials. Uniform jobs: (batch, 64-row q-tile, 256-key
// chunk) -> 144 jobs/batch, 576 total. sPt ALIASES sKt (K dead after S).
// smem = (4096 + 8704 + 8192) floats = 82KB -> 2 blocks/SM.
// ---------------------------------------------------------------------------
#define PQ2 64
#define PK2 136      // K tile pitch (>=128 keys!)  64*136 = 8704 floats
#define PV2 64
#define PP2 68       // P tile pitch; 128*68 = 8704 floats (same region as K)

#define A_QT 0
#define A_KP (A_QT + 64 * PQ2)
#define A_V  (A_KP + 8704)
#define ATTN_SMEM ((A_V + 128 * PV2) * 4)

__device__ __forceinline__ float softmax_row(float* sv, int qi, int k0, int lane,
                                             const int* sPad, float& mr, float& lr,
                                             float* pout)
{
#pragma unroll
    for (int i = 0; i < 4; i++) {
        const int kj = k0 + lane * 4 + i;
        const bool masked = (kj > qi) || (sPad[lane * 4 + i] == 0);
        sv[i] = (masked ? -1e9f : sv[i]) * 0.125f;
    }
    float tm = fmaxf(fmaxf(sv[0], sv[1]), fmaxf(sv[2], sv[3]));
    tm = fmaxf(tm, __shfl_xor_sync(0xffffffffu, tm, 1));
    tm = fmaxf(tm, __shfl_xor_sync(0xffffffffu, tm, 2));
    tm = fmaxf(tm, __shfl_xor_sync(0xffffffffu, tm, 4));
    tm = fmaxf(tm, __shfl_xor_sync(0xffffffffu, tm, 8));
    tm = fmaxf(tm, __shfl_xor_sync(0xffffffffu, tm, 16));
    const float mnew = fmaxf(mr, tm);
    const float scl = __expf(mr - mnew);
    float tl = 0.f;
#pragma unroll
    for (int i = 0; i < 4; i++) { pout[i] = __expf(sv[i] - mnew); tl += pout[i]; }
    tl += __shfl_xor_sync(0xffffffffu, tl, 1);
    tl += __shfl_xor_sync(0xffffffffu, tl, 2);
    tl += __shfl_xor_sync(0xffffffffu, tl, 4);
    tl += __shfl_xor_sync(0xffffffffu, tl, 8);
    tl += __shfl_xor_sync(0xffffffffu, tl, 16);
    lr = lr * scl + tl;
    mr = mnew;
    return scl;
}

__global__ __launch_bounds__(256, 2) void attn_partial_kernel(
    const int* __restrict__ pad)
{
    // decode job: uniform 256-key chunks
    const int bid = blockIdx.x;
    const int b = bid / 144;
    int rem = bid - b * 144;
    int jq = 0;
    {
        int acc = 0;
        while (true) {
            int nchj = (jq + 4) >> 2;
            if (acc + nchj > rem) { rem -= acc; break; }
            acc += nchj; jq++;
        }
    }
    const int ch = rem;
    const int q0 = jq * 64;
    const int kstart = ch * 256;
    const int kmax = q0 + 64;
    const int kend = (kstart + 256 < kmax) ? kstart + 256 : kmax;
    const int nkt = (kend - kstart + 127) >> 7;

    const int tid  = threadIdx.x;
    const int lane = tid & 31;
    const int ty8  = (tid >> 5) * 8;

    extern __shared__ float smem[];
    float* sQt = smem + A_QT;
    float* sKt = smem + A_KP;     // K tile  [d][key]  pitch PK2
    float* sPt = smem + A_KP;     // P tile  [key][row] pitch PP2 (aliases K)
    float* sV  = smem + A_V;
    __shared__ int sPad[128];

#pragma unroll
    for (int u = 0; u < 4; u++) {
        int idx = tid + u * 256;
        int d = idx >> 4, f = (idx & 15) * 4;
        float4 v4 = *reinterpret_cast<const float4*>(
            &g_qT[(size_t)d * MTOT + b * SEQ + q0 + f]);
        *reinterpret_cast<float4*>(&sQt[d * PQ2 + f]) = v4;
    }

    float m[8], l[8];
    u64 o2[4][2];
#pragma unroll
    for (int r = 0; r < 8; r++) { m[r] = -3.0e38f; l[r] = 0.f; }
#pragma unroll
    for (int p = 0; p < 4; p++) { o2[p][0] = 0ULL; o2[p][1] = 0ULL; }

    for (int kt = 0; kt < nkt; kt++) {
        const int k0 = kstart + kt * 128;
        __syncthreads();   // prev PV reads done before restaging K/V

#pragma unroll
        for (int u = 0; u < 8; u++) {
            int idx = tid + u * 256;
            int d = idx >> 5, f = (idx & 31) * 4;
            float4 v4 = *reinterpret_cast<const float4*>(
                &g_kT[(size_t)d * MTOT + b * SEQ + k0 + f]);
            *reinterpret_cast<float4*>(&sKt[d * PK2 + f]) = v4;
        }
#pragma unroll
        for (int u = 0; u < 8; u++) {
            int idx = tid + u * 256;
            int r = idx >> 4, f = (idx & 15) * 4;
            float4 a = *reinterpret_cast<const float4*>(
                &g_vs[((size_t)b * SEQ + k0 + r) * HD + f]);
            *reinterpret_cast<float4*>(&sV[r * PV2 + f]) = a;
        }
        if (tid < 128) sPad[tid] = pad[b * SEQ + k0 + tid];
        __syncthreads();

        // S = Q K^T
        u64 s2[4][4];
#pragma unroll
        for (int p = 0; p < 4; p++)
#pragma unroll
            for (int i = 0; i < 4; i++) s2[p][i] = 0ULL;
#pragma unroll 8
        for (int d = 0; d < 64; d++) {
            ulonglong2 qA = *reinterpret_cast<const ulonglong2*>(&sQt[d * PQ2 + ty8]);
            ulonglong2 qB = *reinterpret_cast<const ulonglong2*>(&sQt[d * PQ2 + ty8 + 4]);
            float4 kv = *reinterpret_cast<const float4*>(&sKt[d * PK2 + lane * 4]);
            u64 k0s = splat2(kv.x), k1s = splat2(kv.y);
            u64 k2s = splat2(kv.z), k3s = splat2(kv.w);
            fma2(s2[0][0], qA.x, k0s); fma2(s2[0][1], qA.x, k1s);
            fma2(s2[0][2], qA.x, k2s); fma2(s2[0][3], qA.x, k3s);
            fma2(s2[1][0], qA.y, k0s); fma2(s2[1][1], qA.y, k1s);
            fma2(s2[1][2], qA.y, k2s); fma2(s2[1][3], qA.y, k3s);
            fma2(s2[2][0], qB.x, k0s); fma2(s2[2][1], qB.x, k1s);
            fma2(s2[2][2], qB.x, k2s); fma2(s2[2][3], qB.x, k3s);
            fma2(s2[3][0], qB.y, k0s); fma2(s2[3][1], qB.y, k1s);
            fma2(s2[3][2], qB.y, k2s); fma2(s2[3][3], qB.y, k3s);
        }
        __syncthreads();   // ALL warps done reading K before P overwrites it

        // mask + softmax, two groups of 4 rows
#pragma unroll
        for (int g = 0; g < 2; g++) {
            float p4[4][4];
#pragma unroll
            for (int pr = 0; pr < 2; pr++) {
                const int p = g * 2 + pr;
                float svA[4], svB[4];
#pragma unroll
                for (int i = 0; i < 4; i++)
                    unpack2(s2[p][i], svA[i], svB[i]);
                const int rA = p * 2, rB = p * 2 + 1;
                float sclA = softmax_row(svA, q0 + ty8 + rA, k0, lane, sPad,
                                         m[rA], l[rA], p4[pr * 2]);
                float sclB = softmax_row(svB, q0 + ty8 + rB, k0, lane, sPad,
                                         m[rB], l[rB], p4[pr * 2 + 1]);
                u64 sp = pack2(sclA, sclB);
                mul2(o2[p][0], sp);
                mul2(o2[p][1], sp);
            }
#pragma unroll
            for (int i = 0; i < 4; i++) {
                const int key = lane * 4 + i;
                *reinterpret_cast<float4*>(&sPt[key * PP2 + ty8 + g * 4]) =
                    make_float4(p4[0][i], p4[1][i], p4[2][i], p4[3][i]);
            }
        }
        __syncthreads();

        // O += P V
#pragma unroll 8
        for (int j = 0; j < 128; j++) {
            ulonglong2 pA = *reinterpret_cast<const ulonglong2*>(&sPt[j * PP2 + ty8]);
            ulonglong2 pB = *reinterpret_cast<const ulonglong2*>(&sPt[j * PP2 + ty8 + 4]);
            float2 v2 = *reinterpret_cast<const float2*>(&sV[j * PV2 + lane * 2]);
            u64 v0 = splat2(v2.x), v1 = splat2(v2.y);
            fma2(o2[0][0], pA.x, v0); fma2(o2[0][1], pA.x, v1);
            fma2(o2[1][0], pA.y, v0); fma2(o2[1][1], pA.y, v1);
            fma2(o2[2][0], pB.x, v0); fma2(o2[2][1], pB.x, v1);
            fma2(o2[3][0], pB.y, v0); fma2(o2[3][1], pB.y, v1);
        }
    }

    if (lane == 0) {
#pragma unroll
        for (int r = 0; r < 8; r++) {
            g_pm[bid * 64 + ty8 + r] = m[r];
            g_pl[bid * 64 + ty8 + r] = l[r];
        }
    }
#pragma unroll
    for (int p = 0; p < 4; p++) {
        float aLo, aHi, bLo, bHi;
        unpack2(o2[p][0], aLo, aHi);
        unpack2(o2[p][1], bLo, bHi);
        *reinterpret_cast<float2*>(
            &g_po[(size_t)bid * 4096 + (ty8 + 2 * p) * 64 + lane * 2]) =
            make_float2(aLo, bLo);
        *reinterpret_cast<float2*>(
            &g_po[(size_t)bid * 4096 + (ty8 + 2 * p + 1) * 64 + lane * 2]) =
            make_float2(aHi, bHi);
    }
}

// ---------------------------------------------------------------------------
// Kernel F: merge partials (up to 8 chunks per q-tile).
// ---------------------------------------------------------------------------
__global__ __launch_bounds__(256) void attn_merge_kernel(float* __restrict__ out)
{
    const int b  = blockIdx.x >> 5;
    const int jq = blockIdx.x & 31;
    int off = 0;
    for (int j = 0; j < jq; j++) off += (j + 4) >> 2;
    const int nch = (jq + 4) >> 2;
    const int jbase = b * 144 + off;
    const int q0 = jq * 64;

    const int d  = threadIdx.x & 63;
    const int r0 = threadIdx.x >> 6;

    for (int rr = 0; rr < 16; rr++) {
        const int row = r0 + rr * 4;
        float M = -3.0e38f;
        for (int i = 0; i < nch; i++)
            M = fmaxf(M, g_pm[(jbase + i) * 64 + row]);
        float L = 0.f, O = 0.f;
        for (int i = 0; i < nch; i++) {
            float mi = g_pm[(jbase + i) * 64 + row];
            float li = g_pl[(jbase + i) * 64 + row];
            float w = __expf(mi - M);
            L += li * w;
            O += g_po[(size_t)(jbase + i) * 4096 + row * 64 + d] * w;
        }
        float res = (M <= -1.0e8f) ? g_vmean[b * HD + d] : O / L;
        out[((size_t)b * SEQ + q0 + row) * HD + d] = res;
    }
}

// ---------------------------------------------------------------------------
extern "C" void kernel_launch(void* const* d_in, const int* in_sizes, int n_in,
                              void* d_out, int out_size)
{
    const float* x   = (const float*)d_in[0];
    const int*   pad = (const int*)  d_in[1];
    const float* Wq  = (const float*)d_in[2];
    const float* Wk  = (const float*)d_in[3];
    const float* Wv  = (const float*)d_in[4];
    float* out = (float*)d_out;

    cudaFuncSetAttribute(qkv_gemm_kernel,
                         cudaFuncAttributeMaxDynamicSharedMemorySize, GEMM_SMEM);
    cudaFuncSetAttribute(attn_partial_kernel,
                         cudaFuncAttributeMaxDynamicSharedMemorySize, ATTN_SMEM);

    convert_w_kernel<<<192, 256>>>(Wq, Wk, Wv);
    qkv_gemm_kernel<<<128, 256, GEMM_SMEM>>>(x);
    vmean1_kernel<<<dim3(BSZ, 32), 256>>>();
    vmean2_kernel<<<BSZ, 256>>>();
    attn_partial_kernel<<<NJOBS, 256, ATTN_SMEM>>>(pad);
    attn_merge_kernel<<<128, 256>>>(out);
}